// round 12
// baseline (speedup 1.0000x reference)
#include <cuda_runtime.h>
#include <cuda_bf16.h>

// Problem constants (GatedMessageGcn_3126736191774)
#define RR   1000          // number of relations
#define DD   100           // feature dim
#define MM   2000000       // num_messages (segments)
#define EMAX 16000000      // edges

// ---------------------------------------------------------------------------
// Device scratch (static; no runtime allocation allowed)
// ---------------------------------------------------------------------------
__device__ float g_table[RR * RR];   // sigmoid(Gs @ Gr^T), 4 MB (L2-resident)
__device__ float g_denom[MM];        // segment sums, 8 MB   (L2-resident)
__device__ int   g_recv[EMAX];       // compacted receiver idx, 64 MB

// ---------------------------------------------------------------------------
// Kernel 1: 64x64-tile GEMM (K=100) + sigmoid, transposed smem, software-
//   pipelined k-loop: LDS.128 for step k+1 issue before step k's 16 FFMAs,
//   hiding the 29-cyc LDS latency. Staging uses float4 global loads.
// ---------------------------------------------------------------------------
#define RPAD 68   // row pad: 68*4B = 272B, 16B-aligned strides

__global__ void __launch_bounds__(256)
gemm_sigmoid_kernel(const float* __restrict__ Gs,
                    const float* __restrict__ Gr) {
    __shared__ __align__(16) float As[DD * RPAD];   // [k][row] sender
    __shared__ __align__(16) float Bs[DD * RPAD];   // [k][row] receiver

    const int tid = threadIdx.x;
    const int i0 = blockIdx.y * 64;
    const int j0 = blockIdx.x * 64;

    // Stage: global [row][k] -> smem [k][row], float4 global loads.
    // 64 rows x 25 float4 = 1600 vec-loads; 256 threads -> ~7 each.
    for (int idx = tid; idx < 64 * (DD / 4); idx += 256) {
        int row = idx / (DD / 4);
        int kq  = idx % (DD / 4);          // k quad index
        int gi = i0 + row;
        int gj = j0 + row;
        float4 av = (gi < RR)
            ? *reinterpret_cast<const float4*>(&Gs[gi * DD + 4 * kq])
            : make_float4(0, 0, 0, 0);
        float4 bv = (gj < RR)
            ? *reinterpret_cast<const float4*>(&Gr[gj * DD + 4 * kq])
            : make_float4(0, 0, 0, 0);
        int k = 4 * kq;
        As[(k    ) * RPAD + row] = av.x;
        As[(k + 1) * RPAD + row] = av.y;
        As[(k + 2) * RPAD + row] = av.z;
        As[(k + 3) * RPAD + row] = av.w;
        Bs[(k    ) * RPAD + row] = bv.x;
        Bs[(k + 1) * RPAD + row] = bv.y;
        Bs[(k + 2) * RPAD + row] = bv.z;
        Bs[(k + 3) * RPAD + row] = bv.w;
    }
    __syncthreads();

    const int tx = tid & 15;   // cols 4tx .. 4tx+3 (contiguous)
    const int ty = tid >> 4;   // rows 4ty .. 4ty+3 (contiguous)
    const float* Arow = &As[4 * ty];
    const float* Brow = &Bs[4 * tx];

    float acc[4][4];
    #pragma unroll
    for (int m = 0; m < 4; m++)
        #pragma unroll
        for (int n = 0; n < 4; n++) acc[m][n] = 0.0f;

    // Software-pipelined k-loop: prefetch k+1 before computing k.
    float4 a = *reinterpret_cast<const float4*>(&Arow[0]);
    float4 b = *reinterpret_cast<const float4*>(&Brow[0]);

    #pragma unroll 4
    for (int k = 0; k < DD - 1; k++) {
        float4 a2 = *reinterpret_cast<const float4*>(&Arow[(k + 1) * RPAD]);
        float4 b2 = *reinterpret_cast<const float4*>(&Brow[(k + 1) * RPAD]);

        acc[0][0] += a.x * b.x; acc[0][1] += a.x * b.y; acc[0][2] += a.x * b.z; acc[0][3] += a.x * b.w;
        acc[1][0] += a.y * b.x; acc[1][1] += a.y * b.y; acc[1][2] += a.y * b.z; acc[1][3] += a.y * b.w;
        acc[2][0] += a.z * b.x; acc[2][1] += a.z * b.y; acc[2][2] += a.z * b.z; acc[2][3] += a.z * b.w;
        acc[3][0] += a.w * b.x; acc[3][1] += a.w * b.y; acc[3][2] += a.w * b.z; acc[3][3] += a.w * b.w;

        a = a2; b = b2;
    }
    // final k = DD-1
    acc[0][0] += a.x * b.x; acc[0][1] += a.x * b.y; acc[0][2] += a.x * b.z; acc[0][3] += a.x * b.w;
    acc[1][0] += a.y * b.x; acc[1][1] += a.y * b.y; acc[1][2] += a.y * b.z; acc[1][3] += a.y * b.w;
    acc[2][0] += a.z * b.x; acc[2][1] += a.z * b.y; acc[2][2] += a.z * b.z; acc[2][3] += a.z * b.w;
    acc[3][0] += a.w * b.x; acc[3][1] += a.w * b.y; acc[3][2] += a.w * b.z; acc[3][3] += a.w * b.w;

    const int jb = j0 + 4 * tx;
    #pragma unroll
    for (int m = 0; m < 4; m++) {
        int i = i0 + 4 * ty + m;
        if (i >= RR) continue;
        float4 v;
        v.x = 1.0f / (1.0f + __expf(-acc[m][0]));
        v.y = 1.0f / (1.0f + __expf(-acc[m][1]));
        v.z = 1.0f / (1.0f + __expf(-acc[m][2]));
        v.w = 1.0f / (1.0f + __expf(-acc[m][3]));
        if (jb + 3 < RR) {
            *reinterpret_cast<float4*>(&g_table[i * RR + jb]) = v;  // 16B aligned
        } else {
            float vv[4] = {v.x, v.y, v.z, v.w};
            #pragma unroll
            for (int n = 0; n < 4; n++)
                if (jb + n < RR) g_table[i * RR + jb + n] = vv[n];
        }
    }
}

// ---------------------------------------------------------------------------
// Kernel 2 (pass 1): 4 edges/thread (champion config — frozen).
// ---------------------------------------------------------------------------
__global__ void edge_pass1_kernel(const int4* __restrict__ rel4,
                                  const int4* __restrict__ msg4,
                                  float4* __restrict__ gates4,
                                  int E4) {
    int t = blockIdx.x * blockDim.x + threadIdx.x;
    if (t >= E4) return;

    int4 ra = rel4[2 * t];
    int4 rb = rel4[2 * t + 1];
    int4 ma = msg4[2 * t];
    int4 mb = msg4[2 * t + 1];

    float g0 = __ldg(&g_table[ra.x * RR + ra.y]);
    float g1 = __ldg(&g_table[ra.z * RR + ra.w]);
    float g2 = __ldg(&g_table[rb.x * RR + rb.y]);
    float g3 = __ldg(&g_table[rb.z * RR + rb.w]);

    gates4[t] = make_float4(g0, g1, g2, g3);
    reinterpret_cast<int4*>(g_recv)[t] = make_int4(ma.y, ma.w, mb.y, mb.w);

    atomicAdd(&g_denom[ma.y], g0);   // return unused -> REDG
    atomicAdd(&g_denom[ma.w], g1);
    atomicAdd(&g_denom[mb.y], g2);
    atomicAdd(&g_denom[mb.w], g3);
}

// ---------------------------------------------------------------------------
// Kernel 3 (pass 2): weights = gate / (denom[recv] + 1e-8), 4 edges/thread
// ---------------------------------------------------------------------------
__global__ void edge_pass2_kernel(float4* __restrict__ out4, int E4) {
    int t = blockIdx.x * blockDim.x + threadIdx.x;
    if (t >= E4) return;

    int4   r = reinterpret_cast<const int4*>(g_recv)[t];
    float4 g = out4[t];

    float d0 = __ldg(&g_denom[r.x]);
    float d1 = __ldg(&g_denom[r.y]);
    float d2 = __ldg(&g_denom[r.z]);
    float d3 = __ldg(&g_denom[r.w]);

    out4[t] = make_float4(g.x / (d0 + 1e-8f), g.y / (d1 + 1e-8f),
                          g.z / (d2 + 1e-8f), g.w / (d3 + 1e-8f));
}

// ---------------------------------------------------------------------------
// Scalar tails (E % 4 != 0 safety; E=16M so normally empty)
// ---------------------------------------------------------------------------
__global__ void edge_tail_kernel(const int2* __restrict__ rel,
                                 const int2* __restrict__ msg,
                                 float* __restrict__ gates,
                                 int start, int E) {
    int e = start + blockIdx.x * blockDim.x + threadIdx.x;
    if (e >= E) return;
    int2 rp = rel[e];
    int  rv = msg[e].y;
    float g = __ldg(&g_table[rp.x * RR + rp.y]);
    gates[e] = g;
    g_recv[e] = rv;
    atomicAdd(&g_denom[rv], g);
}

__global__ void edge_tail2_kernel(float* __restrict__ out,
                                  int start, int E) {
    int e = start + blockIdx.x * blockDim.x + threadIdx.x;
    if (e >= E) return;
    out[e] = out[e] / (__ldg(&g_denom[g_recv[e]]) + 1e-8f);
}

// ---------------------------------------------------------------------------
// Host helper: cached symbol address for memset (defined BEFORE use)
// ---------------------------------------------------------------------------
static void* denom_device_addr() {
    static void* p = nullptr;
    if (!p) cudaGetSymbolAddress(&p, g_denom);
    return p;
}

// ---------------------------------------------------------------------------
// Launch
// ---------------------------------------------------------------------------
extern "C" void kernel_launch(void* const* d_in, const int* in_sizes, int n_in,
                              void* d_out, int out_size) {
    const float* Gs = (const float*)d_in[0];
    const float* Gr = (const float*)d_in[1];
    const int4*  rel4 = (const int4*)d_in[2];
    const int4*  msg4 = (const int4*)d_in[3];
    float* out = (float*)d_out;

    int E  = in_sizes[2] / 2;   // (E,2) index pairs
    int E4 = E / 4;
    int tail = E - E4 * 4;

    // 1. zero denom (graph-capturable async memset)
    cudaMemsetAsync(denom_device_addr(), 0, (size_t)MM * sizeof(float));

    // 2. gate table (64x64 GEMM, pipelined k-loop)
    dim3 ggrid((RR + 63) / 64, (RR + 63) / 64);
    gemm_sigmoid_kernel<<<ggrid, 256>>>(Gs, Gr);

    // 3. pass 1: gates + segment sum
    int nblk = (E4 + 255) / 256;
    edge_pass1_kernel<<<nblk, 256>>>(rel4, msg4, (float4*)out, E4);
    if (tail) {
        edge_tail_kernel<<<1, 256>>>((const int2*)d_in[2], (const int2*)d_in[3],
                                     out, E4 * 4, E);
    }

    // 4. pass 2: normalize
    edge_pass2_kernel<<<nblk, 256>>>((float4*)out, E4);
    if (tail) {
        edge_tail2_kernel<<<1, 256>>>(out, E4 * 4, E);
    }
}